// round 1
// baseline (speedup 1.0000x reference)
#include <cuda_runtime.h>
#include <math.h>

#define DZ 32
#define DA 16
#define KMIX 8
#define DH 64
#define DG 64
#define TT 128
#define NB 256
#define LD 33    // padded stride for 32-col matrices
#define LDK 17   // padded stride for K (32x16)

// output offsets (elements), per flattened reference tuple
#define OFF_ZF  0ull
#define OFF_PF  1048576ull
#define OFF_ZP  34603008ull
#define OFF_AF  35651584ull
#define OFF_AP  36175872ull
#define OFF_PP  36700160ull
#define OFF_ALP 70254592ull
#define OFF_AL  70516736ull
#define OFF_CL  104071168ull
#define OFF_ZM  120848384ull
#define OFF_LT  121896960ull
#define OFF_S   155451392ull

__device__ __forceinline__ float sigmoidf_(float x){ return 1.0f/(1.0f+expf(-x)); }

// GRU cell + softmax + mixture build. Writes alpha[], Anew/Cnew (padded), updates hcur.
__device__ __forceinline__ void gru_alpha_mix(
    int tid, const float* ak, const float* h_ctx, float* hcur, float* hnew,
    float* gx, float* gh, float* alpha, float* Anew, float* Cnew,
    const float* __restrict__ Wx, const float* __restrict__ Wh,
    const float* __restrict__ bb, const float* __restrict__ Wo,
    const float* __restrict__ bo,
    const float* __restrict__ Amat, const float* __restrict__ Cmat)
{
    if (tid < 192) {
        float s = bb[tid];
        #pragma unroll
        for (int i = 0; i < DA; i++) s += ak[i] * Wx[i*192 + tid];
        #pragma unroll 8
        for (int d = 0; d < DH; d++) s += h_ctx[d] * Wx[(DA+d)*192 + tid];
        gx[tid] = s;
        float sh = 0.f;
        #pragma unroll 8
        for (int d = 0; d < DH; d++) sh += hcur[d] * Wh[d*192 + tid];
        gh[tid] = sh;
    }
    __syncthreads();
    if (tid < DG) {
        float r = sigmoidf_(gx[tid] + gh[tid]);
        float u = sigmoidf_(gx[64+tid] + gh[64+tid]);
        float n = tanhf(gx[128+tid] + r * gh[128+tid]);
        hnew[tid] = (1.f - u) * n + u * hcur[tid];
    }
    __syncthreads();
    if (tid < KMIX) {
        float s = bo[tid];
        #pragma unroll 8
        for (int d = 0; d < DG; d++) s += hnew[d] * Wo[d*KMIX + tid];
        gx[tid] = s;  // reuse gx as logits
    }
    __syncthreads();
    if (tid == 0) {
        float m = gx[0];
        #pragma unroll
        for (int k = 1; k < KMIX; k++) m = fmaxf(m, gx[k]);
        float e[KMIX]; float sum = 0.f;
        #pragma unroll
        for (int k = 0; k < KMIX; k++) { e[k] = expf(gx[k]-m); sum += e[k]; }
        float inv = 1.f / sum;
        #pragma unroll
        for (int k = 0; k < KMIX; k++) alpha[k] = e[k]*inv;
    }
    __syncthreads();
    // mixture; also commit GRU hidden state (no reader of hcur in this phase)
    for (int e = tid; e < DZ*DZ; e += 256) {
        int i = e >> 5, j = e & 31;
        float s = 0.f;
        #pragma unroll
        for (int k = 0; k < KMIX; k++) s += alpha[k] * Amat[k*(DZ*DZ) + e];
        Anew[i*LD + j] = s;
    }
    for (int e = tid; e < DA*DZ; e += 256) {
        int i = e >> 5, j = e & 31;
        float s = 0.f;
        #pragma unroll
        for (int k = 0; k < KMIX; k++) s += alpha[k] * Cmat[k*(DA*DZ) + e];
        Cnew[i*LD + j] = s;
    }
    if (tid < DG) hcur[tid] = hnew[tid];
    __syncthreads();
}

__global__ __launch_bounds__(256, 2)
void kf_kernel(const float* __restrict__ a_seq, const float* __restrict__ h_obs,
               const float* __restrict__ Amat, const float* __restrict__ Cmat,
               const float* __restrict__ a0,   const float* __restrict__ Wx,
               const float* __restrict__ Wh,   const float* __restrict__ bb,
               const float* __restrict__ Wo,   const float* __restrict__ bo,
               float* __restrict__ out)
{
    __shared__ float h_ctx[DH], hcur[DH], hnew[DH];
    __shared__ float ak[DA];
    __shared__ float gx[192], gh[192];
    __shared__ float alpha[KMIX];
    __shared__ float Acur[DZ*LD], Ccur[DA*LD], Anew[DZ*LD], Cnew[DA*LD];
    __shared__ float zf[DZ], znew[DZ], zfn[DZ], rvec[DA], zp[DZ], afl[DA], apr[DA];
    __shared__ float P[DZ*LD], CPs[DA*LD], SG[DA*LD];
    __shared__ float prow[DZ], fac[DA], scal;
    __shared__ float Kg[DZ*LDK], IKC[DZ*LD], Mb[DZ*LD], Pf[DZ*LD], CH[DZ*LD];

    const int tid = threadIdx.x;
    const int b   = blockIdx.x;

    // --- prologue: h_ctx (mean over T), zero state, P0 = 10 I
    if (tid < DH) {
        float s = 0.f;
        const float* hp = h_obs + (size_t)b*TT*DH + tid;
        #pragma unroll 4
        for (int t = 0; t < TT; t++) s += hp[t*DH];
        h_ctx[tid] = s * (1.0f/TT);
        hcur[tid]  = 0.f;
    }
    if (tid < DA) ak[tid] = a0[tid];
    for (int e = tid; e < DZ*DZ; e += 256) {
        int i = e >> 5, j = e & 31;
        P[i*LD + j] = (i == j) ? 10.f : 0.f;
    }
    if (tid < DZ) zf[tid] = 0.f;
    __syncthreads();

    // initial alpha step -> Acur/Ccur
    gru_alpha_mix(tid, ak, h_ctx, hcur, hnew, gx, gh, alpha, Acur, Ccur,
                  Wx, Wh, bb, Wo, bo, Amat, Cmat);

    for (int t = 0; t < TT; t++) {
        const size_t bt = (size_t)b*TT + t;
        // observation
        if (tid < DA) ak[tid] = a_seq[bt*DA + tid];
        __syncthreads();

        // alpha chain for THIS step (uses true obs a_k) -> Anew/Cnew, alpha
        gru_alpha_mix(tid, ak, h_ctx, hcur, hnew, gx, gh, alpha, Anew, Cnew,
                      Wx, Wh, bb, Wo, bo, Amat, Cmat);

        // predict with carry mixture: z = Acur * z_prev
        if (tid < DZ) {
            float s = 0.f;
            #pragma unroll
            for (int j = 0; j < DZ; j++) s += Acur[tid*LD + j] * zf[j];
            znew[tid] = s;
        }
        __syncthreads();
        // residual r = a_k - C z ; CP = Ccur * P (independent, same phase)
        if (tid < DA) {
            float s = 0.f;
            #pragma unroll
            for (int j = 0; j < DZ; j++) s += Ccur[tid*LD + j] * znew[j];
            rvec[tid] = ak[tid] - s;
        }
        for (int e = tid; e < DA*DZ; e += 256) {
            int i = e >> 5, j = e & 31;
            float s = 0.f;
            #pragma unroll
            for (int m = 0; m < DZ; m++) s += Ccur[i*LD + m] * P[m*LD + j];
            CPs[i*LD + j] = s;
        }
        __syncthreads();
        // S = CP C^T + 0.3 I  (write S_pred out now; GJ destroys it). Augment identity.
        {
            int i = tid >> 4, j = tid & 15;
            float s = (i == j) ? 0.3f : 0.f;
            #pragma unroll
            for (int m = 0; m < DZ; m++) s += CPs[i*LD + m] * Ccur[j*LD + m];
            SG[i*LD + j]      = s;
            SG[i*LD + 16 + j] = (i == j) ? 1.f : 0.f;
            out[OFF_S + bt*256 + tid] = s;
        }
        __syncthreads();
        // Gauss-Jordan invert S (SPD, diag-dominant; no pivoting needed)
        for (int p = 0; p < DA; p++) {
            if (tid < 32)       prow[tid]      = SG[p*LD + tid];
            else if (tid < 48)  fac[tid - 32]  = SG[(tid-32)*LD + p];
            else if (tid == 48) scal           = 1.0f / SG[p*LD + p];
            __syncthreads();
            {
                int i = tid >> 5, j = tid & 31;
                float pv = prow[j] * scal;
                if (i  == p) SG[i*LD + j]  = pv; else SG[i*LD + j]  -= fac[i]  * pv;
                int i2 = i + 8;
                if (i2 == p) SG[i2*LD + j] = pv; else SG[i2*LD + j] -= fac[i2] * pv;
            }
            __syncthreads();
        }
        // K = P C^T S^{-1} = (CP)^T * Sinv
        for (int e = tid; e < DZ*DA; e += 256) {
            int i = e >> 4, j = e & 15;
            float s = 0.f;
            #pragma unroll
            for (int m = 0; m < DA; m++) s += CPs[m*LD + i] * SG[m*LD + 16 + j];
            Kg[i*LDK + j] = s;
        }
        __syncthreads();
        // IKC = I - K C
        for (int e = tid; e < DZ*DZ; e += 256) {
            int i = e >> 5, j = e & 31;
            float s = (i == j) ? 1.f : 0.f;
            #pragma unroll
            for (int m = 0; m < DA; m++) s -= Kg[i*LDK + m] * Ccur[m*LD + j];
            IKC[i*LD + j] = s;
        }
        __syncthreads();
        // M = IKC * P ; z_f = z + K r
        for (int e = tid; e < DZ*DZ; e += 256) {
            int i = e >> 5, j = e & 31;
            float s = 0.f;
            #pragma unroll
            for (int m = 0; m < DZ; m++) s += IKC[i*LD + m] * P[m*LD + j];
            Mb[i*LD + j] = s;
        }
        if (tid < DZ) {
            float s = znew[tid];
            #pragma unroll
            for (int m = 0; m < DA; m++) s += Kg[tid*LDK + m] * rvec[m];
            zfn[tid] = s;
        }
        __syncthreads();
        // Pf_raw = M IKC^T + 0.3 K K^T  (into CH) ; a_filt = C z_f
        for (int e = tid; e < DZ*DZ; e += 256) {
            int i = e >> 5, j = e & 31;
            float s = 0.f;
            #pragma unroll
            for (int m = 0; m < DZ; m++) s += Mb[i*LD + m] * IKC[j*LD + m];
            float s2 = 0.f;
            #pragma unroll
            for (int m = 0; m < DA; m++) s2 += Kg[i*LDK + m] * Kg[j*LDK + m];
            CH[i*LD + j] = s + 0.3f * s2;
        }
        if (tid < DA) {
            float s = 0.f;
            #pragma unroll
            for (int m = 0; m < DZ; m++) s += Ccur[tid*LD + m] * zfn[m];
            afl[tid] = s;
        }
        __syncthreads();
        // Pf = sym(raw) ; z_pred = Anew z_f
        for (int e = tid; e < DZ*DZ; e += 256) {
            int i = e >> 5, j = e & 31;
            Pf[i*LD + j] = 0.5f * (CH[i*LD + j] + CH[j*LD + i]);
        }
        if (tid < DZ) {
            float s = 0.f;
            #pragma unroll
            for (int m = 0; m < DZ; m++) s += Anew[tid*LD + m] * zfn[m];
            zp[tid] = s;
        }
        __syncthreads();
        // CH := Pf + 2e-4 I (chol workspace) ; M2 = Anew * Pf ; a_pred = Cnew z_pred
        for (int e = tid; e < DZ*DZ; e += 256) {
            int i = e >> 5, j = e & 31;
            CH[i*LD + j] = Pf[i*LD + j] + ((i == j) ? 2e-4f : 0.f);
            float s = 0.f;
            #pragma unroll
            for (int m = 0; m < DZ; m++) s += Anew[i*LD + m] * Pf[m*LD + j];
            Mb[i*LD + j] = s;
        }
        if (tid < DA) {
            float s = 0.f;
            #pragma unroll
            for (int m = 0; m < DZ; m++) s += Cnew[tid*LD + m] * zp[m];
            apr[tid] = s;
        }
        __syncthreads();
        // Pp_raw = M2 Anew^T + 0.2 I (into IKC buffer, free now)
        for (int e = tid; e < DZ*DZ; e += 256) {
            int i = e >> 5, j = e & 31;
            float s = (i == j) ? 0.2f : 0.f;
            #pragma unroll
            for (int m = 0; m < DZ; m++) s += Mb[i*LD + m] * Anew[j*LD + m];
            IKC[i*LD + j] = s;
        }
        __syncthreads();
        // P (carry) = sym(Pp_raw) — fused with first Cholesky trailing phase below
        for (int e = tid; e < DZ*DZ; e += 256) {
            int i = e >> 5, j = e & 31;
            P[i*LD + j] = 0.5f * (IKC[i*LD + j] + IKC[j*LD + i]);
        }
        // Cholesky (LDL-style trailing, 1 sync/column; only the L OUTPUT depends
        // on this, not the recursion, so fast reciprocal/rsqrt are safe)
        for (int j = 0; j < DZ-1; j++) {
            float s = __fdividef(1.0f, CH[j*LD + j]);  // column j diag is final
            int n = DZ - 1 - j;
            for (int e = tid; e < n*n; e += 256) {
                int ii = j + 1 + e / n, kk = j + 1 + e % n;
                if (kk <= ii)
                    CH[ii*LD + kk] -= CH[ii*LD + j] * CH[kk*LD + j] * s;
            }
            __syncthreads();
        }

        // ---- outputs ----
        for (int e = tid; e < DZ*DZ; e += 256) {
            int i = e >> 5, j = e & 31;
            out[OFF_PF + bt*1024 + e] = Pf[i*LD + j];
            out[OFF_PP + bt*1024 + e] = P[i*LD + j];
            out[OFF_AL + bt*1024 + e] = Anew[i*LD + j];
            float l;
            if (j < i)       l = CH[i*LD + j] * rsqrtf(CH[j*LD + j]);
            else if (j == i) l = sqrtf(CH[i*LD + i]);
            else             l = 0.f;
            out[OFF_LT + bt*1024 + e] = l;
        }
        for (int e = tid; e < DA*DZ; e += 256) {
            int i = e >> 5, j = e & 31;
            out[OFF_CL + bt*512 + e] = Ccur[i*LD + j];  // OLD C (carry), per reference
        }
        if (tid < DZ) {
            out[OFF_ZF + bt*32 + tid] = zfn[tid];
            out[OFF_ZM + bt*32 + tid] = zfn[tid];
            out[OFF_ZP + bt*32 + tid] = zp[tid];
        } else if (tid < DZ + DA) {
            out[OFF_AF + bt*16 + (tid - DZ)] = afl[tid - DZ];
        } else if (tid < 64) {
            out[OFF_AP + bt*16 + (tid - 48)] = apr[tid - 48];
        } else if (tid < 72) {
            out[OFF_ALP + bt*8 + (tid - 64)] = alpha[tid - 64];
        }
        __syncthreads();  // outputs (read Ccur) before carry overwrite

        // ---- carry ----
        for (int e = tid; e < DZ*DZ; e += 256) {
            int i = e >> 5, j = e & 31;
            Acur[i*LD + j] = Anew[i*LD + j];
        }
        for (int e = tid; e < DA*DZ; e += 256) {
            int i = e >> 5, j = e & 31;
            Ccur[i*LD + j] = Cnew[i*LD + j];
        }
        if (tid < DZ) zf[tid] = zfn[tid];
        __syncthreads();
    }
}

extern "C" void kernel_launch(void* const* d_in, const int* in_sizes, int n_in,
                              void* d_out, int out_size) {
    const float* a_seq = (const float*)d_in[0];
    const float* h_obs = (const float*)d_in[1];
    const float* Amat  = (const float*)d_in[2];
    const float* Cmat  = (const float*)d_in[3];
    const float* a0    = (const float*)d_in[4];
    const float* Wx    = (const float*)d_in[5];
    const float* Wh    = (const float*)d_in[6];
    const float* bb    = (const float*)d_in[7];
    const float* Wo    = (const float*)d_in[8];
    const float* bo    = (const float*)d_in[9];
    float* out = (float*)d_out;
    kf_kernel<<<NB, 256>>>(a_seq, h_obs, Amat, Cmat, a0, Wx, Wh, bb, Wo, bo, out);
}

// round 2
// speedup vs baseline: 1.0980x; 1.0980x over previous
#include <cuda_runtime.h>
#include <math.h>

#define DZ 32
#define DA 16
#define KMIX 8
#define DH 64
#define DG 64
#define TT 128
#define NB 256
#define LD 33    // padded stride for 32-col matrices
#define LDK 17   // padded stride for K (32x16)
#define NSLOT 129

// output offsets (elements), per flattened reference tuple
#define OFF_ZF  0ull
#define OFF_PF  1048576ull
#define OFF_ZP  34603008ull
#define OFF_AF  35651584ull
#define OFF_AP  36175872ull
#define OFF_PP  36700160ull
#define OFF_ALP 70254592ull
#define OFF_AL  70516736ull
#define OFF_CL  104071168ull
#define OFF_ZM  120848384ull
#define OFF_LT  121896960ull
#define OFF_S   155451392ull

// scratch: precomputed gx rows (B x 129 x 192) and h_ctx (B x 64)
__device__ float g_gx[(size_t)NB * NSLOT * 192];
__device__ float g_hctx[NB * DH];

__device__ __forceinline__ float sigmoidf_(float x){ return 1.0f/(1.0f+expf(-x)); }

// ---------------- kernel A: h_ctx = mean_t h_obs ----------------
__global__ void hctx_kernel(const float* __restrict__ h_obs) {
    int b = blockIdx.x, d = threadIdx.x;
    float s = 0.f;
    const float* hp = h_obs + (size_t)b*TT*DH + d;
    #pragma unroll 8
    for (int t = 0; t < TT; t++) s += hp[(size_t)t*DH];
    g_hctx[b*DH + d] = s * (1.0f/TT);
}

// ---------------- kernel B: gx[b][s][g] = [a, h_ctx] @ Wx + b ----------------
__global__ void gx_kernel(const float* __restrict__ a_seq,
                          const float* __restrict__ a0,
                          const float* __restrict__ Wx,
                          const float* __restrict__ bb) {
    __shared__ float xv[80];
    int b = blockIdx.x, s = blockIdx.y, tid = threadIdx.x;
    if (tid < DA)
        xv[tid] = (s == 0) ? a0[tid] : a_seq[((size_t)b*TT + (s-1))*DA + tid];
    else if (tid < 80)
        xv[tid] = g_hctx[b*DH + (tid - DA)];
    __syncthreads();
    float acc = bb[tid];
    #pragma unroll 8
    for (int i = 0; i < 80; i++) acc += xv[i] * Wx[i*192 + tid];
    g_gx[((size_t)b*NSLOT + s)*192 + tid] = acc;
}

// ---------------- main kernel ----------------
__global__ __launch_bounds__(256, 2)
void kf_kernel(const float* __restrict__ a_seq,
               const float* __restrict__ Amat, const float* __restrict__ Cmat,
               const float* __restrict__ Wh,   const float* __restrict__ Wo,
               const float* __restrict__ bo,   float* __restrict__ out)
{
    __shared__ float hcur[DG], hnew[DG], gxs[192], gh[192], aks[DA], alpha[KMIX];
    __shared__ float Acur[DZ*LD], Anew[DZ*LD], P[DZ*LD], RAW[DZ*LD], Pf[DZ*LD], CH[DZ*LD], Xb[DZ*LD];
    __shared__ float Ccur[DA*LD], Cnew[DA*LD], CPs[DA*LD], SG[DA*LD];
    __shared__ float Kg[DZ*LDK];
    __shared__ float zf[DZ], znew[DZ], zfn[DZ], rvec[DA], zp[DZ];

    const int tid  = threadIdx.x;
    const int wid  = tid >> 5;
    const int lane = tid & 31;
    const int b    = blockIdx.x;
    const int tx   = (tid < 32) ? tid : tid - 32;   // index 0..223 for warps 0,2..7

    // ================= prologue =================
    if (tid < DG) hcur[tid] = 0.f;
    if (tid < DZ) zf[tid] = 0.f;
    for (int e = tid; e < DZ*DZ; e += 256) {
        int i = e >> 5, j = e & 31;
        P[i*LD + j] = (i == j) ? 10.f : 0.f;
    }
    if (tid < DG) {  // initial gate: h=0 -> gh=0
        const float* gx0 = g_gx + (size_t)b*NSLOT*192;
        float u = sigmoidf_(gx0[64 + tid]);
        hnew[tid] = (1.f - u) * tanhf(gx0[128 + tid]);
    }
    if (tid >= 224) {  // prefetch gxs slot 1
        int g = tid - 224;
        const float* src = g_gx + ((size_t)b*NSLOT + 1)*192;
        #pragma unroll
        for (int r = 0; r < 6; r++) gxs[g + 32*r] = src[g + 32*r];
    }
    if (tid >= 208 && tid < 224) aks[tid-208] = a_seq[(size_t)b*TT*DA + (tid-208)];
    __syncthreads();
    if (tid < 8) {  // initial logits + softmax
        float lg = bo[tid];
        #pragma unroll 8
        for (int d = 0; d < DG; d++) lg += hnew[d] * Wo[d*KMIX + tid];
        float m = lg;
        #pragma unroll
        for (int o = 4; o; o >>= 1) m = fmaxf(m, __shfl_xor_sync(0xFF, m, o));
        float ev = expf(lg - m);
        float sm = ev;
        #pragma unroll
        for (int o = 4; o; o >>= 1) sm += __shfl_xor_sync(0xFF, sm, o);
        alpha[tid] = ev / sm;
    }
    __syncthreads();
    for (int e = tid; e < DZ*DZ; e += 256) {
        int i = e >> 5, j = e & 31;
        float s = 0.f;
        #pragma unroll
        for (int k = 0; k < KMIX; k++) s += alpha[k] * Amat[k*(DZ*DZ) + e];
        Acur[i*LD + j] = s;
    }
    for (int e = tid; e < DA*DZ; e += 256) {
        int i = e >> 5, j = e & 31;
        float s = 0.f;
        #pragma unroll
        for (int k = 0; k < KMIX; k++) s += alpha[k] * Cmat[k*(DA*DZ) + e];
        Ccur[i*LD + j] = s;
    }
    if (tid < DG) hcur[tid] = hnew[tid];
    __syncthreads();

    // ================= time loop =================
    for (int t = 0; t < TT; t++) {
        const size_t bt = (size_t)b*TT + t;

        // --- ph1: gh (192) || znew (32) ---
        if (tid < 192) {
            float s = 0.f;
            #pragma unroll 8
            for (int d = 0; d < DG; d++) s += hcur[d] * Wh[d*192 + tid];
            gh[tid] = s;
        } else if (tid < 224) {
            int i = tid - 192;
            float s = 0.f;
            #pragma unroll 8
            for (int m = 0; m < DZ; m++) s += Acur[i*LD + m] * zf[m];
            znew[i] = s;
        }
        __syncthreads();

        // --- ph2: gate (64) || CP = Ccur*P (192) ---
        if (tid < DG) {
            float r = sigmoidf_(gxs[tid]       + gh[tid]);
            float u = sigmoidf_(gxs[64 + tid]  + gh[64 + tid]);
            float n = tanhf   (gxs[128 + tid] + r * gh[128 + tid]);
            hnew[tid] = (1.f - u) * n + u * hcur[tid];
        } else {
            for (int e = tid - 64; e < DA*DZ; e += 192) {
                int i = e >> 5, j = e & 31;
                float s = 0.f;
                #pragma unroll 8
                for (int m = 0; m < DZ; m++) s += Ccur[i*LD + m] * P[m*LD + j];
                CPs[i*LD + j] = s;
            }
        }
        __syncthreads();

        // --- ph3: logits/softmax (w0) || rvec (16) || S build + store (208) ---
        if (tid < 32) {
            if (tid < 8) {
                float lg = bo[tid];
                #pragma unroll 8
                for (int d = 0; d < DG; d++) lg += hnew[d] * Wo[d*KMIX + tid];
                float m = lg;
                #pragma unroll
                for (int o = 4; o; o >>= 1) m = fmaxf(m, __shfl_xor_sync(0xFF, m, o));
                float ev = expf(lg - m);
                float sm = ev;
                #pragma unroll
                for (int o = 4; o; o >>= 1) sm += __shfl_xor_sync(0xFF, sm, o);
                alpha[tid] = ev / sm;
            }
        } else if (tid < 48) {
            int i = tid - 32;
            float s = 0.f;
            #pragma unroll 8
            for (int m = 0; m < DZ; m++) s += Ccur[i*LD + m] * znew[m];
            rvec[i] = aks[i] - s;
        } else {
            for (int e = tid - 48; e < DA*DA; e += 208) {
                int i = e >> 4, j = e & 15;
                float s = (i == j) ? 0.3f : 0.f;
                #pragma unroll 8
                for (int m = 0; m < DZ; m++) s += CPs[i*LD + m] * Ccur[j*LD + m];
                SG[i*LD + j] = s;
                out[OFF_S + bt*256 + e] = s;
            }
        }
        __syncthreads();

        // --- ph4: warp1 GJ-invert S (shuffle, no barriers) || mixture + writes (224) ---
        if (wid == 1) {
            float c[16];
            #pragma unroll
            for (int i = 0; i < 16; i++)
                c[i] = (lane < 16) ? SG[i*LD + lane] : ((i == lane-16) ? 1.f : 0.f);
            #pragma unroll
            for (int p = 0; p < 16; p++) {
                float spp = __shfl_sync(0xffffffffu, c[p], p);
                float inv = 1.0f / spp;
                float pivj = c[p] * inv;
                #pragma unroll
                for (int i = 0; i < 16; i++) {
                    float fac = __shfl_sync(0xffffffffu, c[i], p);
                    if (i != p) c[i] -= fac * pivj;
                }
                c[p] = pivj;
            }
            if (lane >= 16) {
                #pragma unroll
                for (int i = 0; i < 16; i++) SG[i*LD + lane] = c[i];
            }
        } else {
            for (int e = tx; e < DZ*DZ; e += 224) {
                int i = e >> 5, j = e & 31;
                float s = 0.f;
                #pragma unroll
                for (int k = 0; k < KMIX; k++) s += alpha[k] * Amat[k*(DZ*DZ) + e];
                Anew[i*LD + j] = s;
                out[OFF_AL + bt*1024 + e] = s;
            }
            for (int e = tx; e < DA*DZ; e += 224) {
                int i = e >> 5, j = e & 31;
                float s = 0.f;
                #pragma unroll
                for (int k = 0; k < KMIX; k++) s += alpha[k] * Cmat[k*(DA*DZ) + e];
                Cnew[i*LD + j] = s;
                out[OFF_CL + bt*512 + e] = Ccur[i*LD + j];  // old C, per reference
            }
            if (tx < DG) hcur[tx] = hnew[tx];
            if (tx >= 64 && tx < 72) out[OFF_ALP + bt*8 + (tx-64)] = alpha[tx-64];
        }
        __syncthreads();

        // --- ph5: K = (CP)^T * Sinv ---
        for (int e = tid; e < DZ*DA; e += 256) {
            int i = e >> 4, j = e & 15;
            float s = 0.f;
            #pragma unroll
            for (int m = 0; m < DA; m++) s += CPs[m*LD + i] * SG[m*LD + 16 + j];
            Kg[i*LDK + j] = s;
        }
        __syncthreads();

        // --- ph6: X = K*CP ; zfn ; prefetch next gx/a ---
        for (int e = tid; e < DZ*DZ; e += 256) {
            int i = e >> 5, j = e & 31;
            float s = 0.f;
            #pragma unroll
            for (int m = 0; m < DA; m++) s += Kg[i*LDK + m] * CPs[m*LD + j];
            Xb[i*LD + j] = s;
        }
        if (tid < DZ) {
            float s = znew[tid];
            #pragma unroll
            for (int m = 0; m < DA; m++) s += Kg[tid*LDK + m] * rvec[m];
            zfn[tid] = s;
        }
        if (tid >= 224 && t + 1 < TT) {
            int g = tid - 224;
            const float* src = g_gx + ((size_t)b*NSLOT + (t+2))*192;
            #pragma unroll
            for (int r = 0; r < 6; r++) gxs[g + 32*r] = src[g + 32*r];
        }
        if (tid >= 208 && tid < 224 && t + 1 < TT)
            aks[tid-208] = a_seq[((size_t)b*TT + t + 1)*DA + (tid-208)];
        __syncthreads();

        // --- ph7: RAW = P - X - X^T + (CP)^T K^T ; afl ; zp ; vec outputs ---
        for (int e = tid; e < DZ*DZ; e += 256) {
            int i = e >> 5, j = e & 31;
            float y = 0.f;
            #pragma unroll
            for (int m = 0; m < DA; m++) y += CPs[m*LD + i] * Kg[j*LDK + m];
            RAW[i*LD + j] = P[i*LD + j] - Xb[i*LD + j] - Xb[j*LD + i] + y;
        }
        if (tid < DA) {
            float s = 0.f;
            #pragma unroll 8
            for (int m = 0; m < DZ; m++) s += Ccur[tid*LD + m] * zfn[m];
            out[OFF_AF + bt*16 + tid] = s;
        } else if (tid < 48) {
            int i = tid - 16;
            float s = 0.f;
            #pragma unroll 8
            for (int m = 0; m < DZ; m++) s += Anew[i*LD + m] * zfn[m];
            zp[i] = s;
            out[OFF_ZP + bt*32 + i] = s;
        }
        if (tid < DZ) {
            out[OFF_ZF + bt*32 + tid] = zfn[tid];
            out[OFF_ZM + bt*32 + tid] = zfn[tid];
        }
        __syncthreads();

        // --- ph8: Pf = sym(RAW); CH = Pf + 2e-4 I; a_pred ---
        for (int e = tid; e < DZ*DZ; e += 256) {
            int i = e >> 5, j = e & 31;
            float v = 0.5f * (RAW[i*LD + j] + RAW[j*LD + i]);
            Pf[i*LD + j] = v;
            CH[i*LD + j] = v + ((i == j) ? 2e-4f : 0.f);
            out[OFF_PF + bt*1024 + e] = v;
        }
        if (tid < DA) {
            float s = 0.f;
            #pragma unroll 8
            for (int m = 0; m < DZ; m++) s += Cnew[tid*LD + m] * zp[m];
            out[OFF_AP + bt*16 + tid] = s;
        }
        __syncthreads();

        // --- ph9-11 (warps 0,2-7 with named barriers) || warp1: Cholesky trailing ---
        if (wid != 1) {
            // ph9: M2 = Anew * Pf
            for (int e = tx; e < DZ*DZ; e += 224) {
                int i = e >> 5, j = e & 31;
                float s = 0.f;
                #pragma unroll 8
                for (int m = 0; m < DZ; m++) s += Anew[i*LD + m] * Pf[m*LD + j];
                Xb[i*LD + j] = s;     // reuse Xb as M2
            }
            asm volatile("bar.sync 1, 224;" ::: "memory");
            // ph10: RAW = M2 * Anew^T + Q
            for (int e = tx; e < DZ*DZ; e += 224) {
                int i = e >> 5, j = e & 31;
                float s = (i == j) ? 0.2f : 0.f;
                #pragma unroll 8
                for (int m = 0; m < DZ; m++) s += Xb[i*LD + m] * Anew[j*LD + m];
                RAW[i*LD + j] = s;
            }
            asm volatile("bar.sync 1, 224;" ::: "memory");
            // ph11: P = sym(RAW); write PP; carries
            for (int e = tx; e < DZ*DZ; e += 224) {
                int i = e >> 5, j = e & 31;
                float v = 0.5f * (RAW[i*LD + j] + RAW[j*LD + i]);
                P[i*LD + j] = v;
                out[OFF_PP + bt*1024 + e] = v;
                Acur[i*LD + j] = Anew[i*LD + j];
            }
            for (int e = tx; e < DA*DZ; e += 224) {
                int i = e >> 5, j = e & 31;
                Ccur[i*LD + j] = Cnew[i*LD + j];
            }
            if (tx < DZ) zf[tx] = zfn[tx];
        } else {
            // Cholesky-style trailing update on CH (warp-synchronous, smem)
            for (int j = 0; j < DZ-1; j++) {
                float inv = __fdividef(1.0f, CH[j*LD + j]);
                int kk = j + 1 + lane;
                if (kk < DZ) {
                    float ckj = CH[kk*LD + j] * inv;
                    for (int ii = kk; ii < DZ; ii++)
                        CH[ii*LD + kk] -= CH[ii*LD + j] * ckj;
                }
                __syncwarp();
            }
        }
        __syncthreads();

        // --- ph12: write L (lower-tri from trailing form) ---
        for (int e = tid; e < DZ*DZ; e += 256) {
            int i = e >> 5, j = e & 31;
            float l;
            if (j < i)       l = CH[i*LD + j] * rsqrtf(CH[j*LD + j]);
            else if (j == i) l = sqrtf(CH[i*LD + i]);
            else             l = 0.f;
            out[OFF_LT + bt*1024 + e] = l;
        }
        // no barrier needed: next ph1 touches disjoint buffers; its end-barrier orders the rest
    }
}

extern "C" void kernel_launch(void* const* d_in, const int* in_sizes, int n_in,
                              void* d_out, int out_size) {
    const float* a_seq = (const float*)d_in[0];
    const float* h_obs = (const float*)d_in[1];
    const float* Amat  = (const float*)d_in[2];
    const float* Cmat  = (const float*)d_in[3];
    const float* a0    = (const float*)d_in[4];
    const float* Wx    = (const float*)d_in[5];
    const float* Wh    = (const float*)d_in[6];
    const float* bb    = (const float*)d_in[7];
    const float* Wo    = (const float*)d_in[8];
    const float* bo    = (const float*)d_in[9];
    float* out = (float*)d_out;

    hctx_kernel<<<NB, DH>>>(h_obs);
    gx_kernel<<<dim3(NB, NSLOT), 192>>>(a_seq, a0, Wx, bb);
    kf_kernel<<<NB, 256>>>(a_seq, Amat, Cmat, Wh, Wo, bo, out);
}